// round 14
// baseline (speedup 1.0000x reference)
#include <cuda_runtime.h>
#include <cuda_fp16.h>
#include <math.h>
#include <stdint.h>

// Problem constants (hardcoded from reference setup_inputs)
#define BATCH   2
#define FRAMES  16
#define SPATIAL 1024            // height*width = 32*32
#define HIDDEN  1024
#define NHEADS  16
#define HDIM    64
#define NTOK    (BATCH*FRAMES*SPATIAL)   // 32768
#define QKV_N   (3*HIDDEN)               // 3072
#define LN_EPS  1e-5f

// Scratch buffers (device globals; no runtime allocation allowed)
__device__ __half g_xn_h[(size_t)NTOK * HIDDEN];      // 64 MB  (fp16, pair-permuted)
__device__ __half g_qkv_h[(size_t)NTOK * QKV_N];      // 201 MB (fp16, natural layout)
__device__ __half g_attn_h[(size_t)NTOK * HIDDEN];    // 64 MB  (fp16, pair-permuted)
__device__ __half g_wqkv_h[(size_t)QKV_N * HIDDEN];   // 6 MB   (fp16, pair-permuted)
__device__ __half g_wout_h[(size_t)HIDDEN * HIDDEN];  // 2 MB   (fp16, pair-permuted)

// Pair-level K-permutation: within each 16-element k-group (8 fp16 pairs),
// pair p -> slot (p<4 ? 2p : 2(p-4)+1). Fragment pairs (t4, t4+4) land adjacent.
__device__ __forceinline__ int pslot(int p) {   // p in 0..7
    return (p < 4) ? (2 * p) : (2 * (p - 4) + 1);
}

__device__ __forceinline__ void cp_async16(uint32_t saddr, const void* gaddr) {
    asm volatile("cp.async.cg.shared.global [%0], [%1], 16;" :: "r"(saddr), "l"(gaddr));
}

// ---------------------------------------------------------------------------
// Weight round+permute: fp32 row-major [rows,1024] -> fp16 pair-permuted.
// ---------------------------------------------------------------------------
__global__ void __launch_bounds__(256) round_perm_w_h(const float* __restrict__ w,
                                                      __half2* __restrict__ out)
{
    const int row = blockIdx.x;
    const int tid = threadIdx.x;
    const float4 v = reinterpret_cast<const float4*>(w + (size_t)row * HIDDEN)[tid];
    const int g16  = tid >> 2;                 // 16-elem group index (8 half2 words)
    const int pl   = 2 * (tid & 3);            // first pair index within group
    __half2* obase = out + (size_t)row * (HIDDEN / 2) + g16 * 8;
    obase[pslot(pl)]     = __floats2half2_rn(v.x, v.y);
    obase[pslot(pl + 1)] = __floats2half2_rn(v.z, v.w);
}

// ---------------------------------------------------------------------------
// LayerNorm: one block per token; output fp16 pair-permuted
// ---------------------------------------------------------------------------
__global__ void __launch_bounds__(256) ln_kernel(const float* __restrict__ x,
                                                 const float* __restrict__ gamma,
                                                 const float* __restrict__ beta)
{
    const int tok = blockIdx.x;
    const int tid = threadIdx.x;
    const float4* xr = reinterpret_cast<const float4*>(x + (size_t)tok * HIDDEN);
    float4 v = xr[tid];

    float s  = v.x + v.y + v.z + v.w;
    float ss = v.x*v.x + v.y*v.y + v.z*v.z + v.w*v.w;

    #pragma unroll
    for (int o = 16; o > 0; o >>= 1) {
        s  += __shfl_xor_sync(0xffffffffu, s,  o);
        ss += __shfl_xor_sync(0xffffffffu, ss, o);
    }
    __shared__ float red_s[8], red_ss[8];
    const int warp = tid >> 5, lane = tid & 31;
    if (lane == 0) { red_s[warp] = s; red_ss[warp] = ss; }
    __syncthreads();
    float fs = 0.f, fss = 0.f;
    #pragma unroll
    for (int i = 0; i < 8; i++) { fs += red_s[i]; fss += red_ss[i]; }

    const float mean = fs * (1.0f / HIDDEN);
    const float var  = fss * (1.0f / HIDDEN) - mean * mean;
    const float inv  = rsqrtf(var + LN_EPS);

    const float4 gm = reinterpret_cast<const float4*>(gamma)[tid];
    const float4 bt = reinterpret_cast<const float4*>(beta)[tid];
    const float o0 = (v.x - mean) * inv * gm.x + bt.x;
    const float o1 = (v.y - mean) * inv * gm.y + bt.y;
    const float o2 = (v.z - mean) * inv * gm.z + bt.z;
    const float o3 = (v.w - mean) * inv * gm.w + bt.w;

    const int g16 = tid >> 2;
    const int pl  = 2 * (tid & 3);
    __half2* obase = reinterpret_cast<__half2*>(g_xn_h) + (size_t)tok * (HIDDEN / 2) + g16 * 8;
    obase[pslot(pl)]     = __floats2half2_rn(o0, o1);
    obase[pslot(pl + 1)] = __floats2half2_rn(o2, o3);
}

// ---------------------------------------------------------------------------
// FP16 mma.sync GEMM (NT), K=1024: C[m][n] = sum_k A[m][k]*B[n][k]
// A, B fp16 pair-permuted. CTA tile 128x128, BK=64 fp16, 128 threads =
// 4 warps (2Mx2N), warp tile 64x64 of m16n8k16. 2-stage cp.async pipeline.
// Register double-buffered fragments: k-step kg+1's LDS issue under kg's MMAs.
// F16OUT: C stored as __half2 (QKV path); else fp32 (final output).
// ---------------------------------------------------------------------------
#define HK      1024
#define HBK     64
#define HNIT    (HK / HBK)      // 16
#define LDTW    40              // 4-byte words per smem row
#define AW      (128 * LDTW)    // words per matrix per stage (5120)
#define STGW    (2 * AW)        // words per stage (A+B)
#define GEMM_SMEM_BYTES (2 * STGW * 4)   // 81920

__device__ __forceinline__ void mma_f16(float c[4],
                                        uint32_t a0, uint32_t a1, uint32_t a2, uint32_t a3,
                                        uint32_t b0, uint32_t b1)
{
    asm volatile(
        "mma.sync.aligned.m16n8k16.row.col.f32.f16.f16.f32 "
        "{%0,%1,%2,%3}, {%4,%5,%6,%7}, {%8,%9}, {%0,%1,%2,%3};"
        : "+f"(c[0]), "+f"(c[1]), "+f"(c[2]), "+f"(c[3])
        : "r"(a0), "r"(a1), "r"(a2), "r"(a3), "r"(b0), "r"(b1));
}

template<bool F16OUT>
__global__ void __launch_bounds__(128, 2)
gemm_h(const __half* __restrict__ A, const __half* __restrict__ B,
       void* __restrict__ Cv, int N)
{
    extern __shared__ uint32_t smem[];   // [2][STGW] words

    const int tid  = threadIdx.x;
    const int wid  = tid >> 5;
    const int lane = tid & 31;
    const int g    = lane >> 2;
    const int t4   = lane & 3;
    const int warpM = wid & 1;        // 0..1 -> 64 rows
    const int warpN = wid >> 1;       // 0..1 -> 64 cols

    const __half* Ab = A + (size_t)blockIdx.y * 128 * HK;
    const __half* Bb = B + (size_t)blockIdx.x * 128 * HK;

    const uint32_t smem_u = (uint32_t)__cvta_generic_to_shared(smem);

    // Loader mapping: per matrix per stage 128 rows x 8 chunks(16B) = 1024;
    // 128 threads -> 8 chunks/thread/matrix.
    int lrow[8], lch[8];
    #pragma unroll
    for (int j = 0; j < 8; j++) {
        const int lin = tid + j * 128;
        lrow[j] = lin >> 3;
        lch[j]  = lin & 7;
    }

    float acc[4][8][4];
    #pragma unroll
    for (int i = 0; i < 4; i++)
        #pragma unroll
        for (int j = 0; j < 8; j++)
            #pragma unroll
            for (int r = 0; r < 4; r++) acc[i][j][r] = 0.f;

    // Prologue: fill stage 0 with tile 0
    #pragma unroll
    for (int j = 0; j < 8; j++) {
        cp_async16(smem_u + (uint32_t)((lrow[j] * LDTW + lch[j] * 4) * 4),
                   Ab + (size_t)lrow[j] * HK + lch[j] * 8);
        cp_async16(smem_u + (uint32_t)((AW + lrow[j] * LDTW + lch[j] * 4) * 4),
                   Bb + (size_t)lrow[j] * HK + lch[j] * 8);
    }
    asm volatile("cp.async.commit_group;" ::: "memory");

    // Fragment double buffers
    uint32_t af[2][4][4];
    uint32_t bf[2][8][2];

    #pragma unroll 1
    for (int it = 0; it < HNIT; it++) {
        const int cur = it & 1;
        const int nxt = cur ^ 1;

        // All warps finished computing stage nxt's previous contents
        __syncthreads();

        // Fill stage nxt with tile it+1 (overlaps MMAs below)
        if (it + 1 < HNIT) {
            const int k0 = (it + 1) * HBK;
            const uint32_t so = (uint32_t)(nxt * STGW) * 4u;
            #pragma unroll
            for (int j = 0; j < 8; j++) {
                cp_async16(smem_u + so + (uint32_t)((lrow[j] * LDTW + lch[j] * 4) * 4),
                           Ab + (size_t)lrow[j] * HK + k0 + lch[j] * 8);
                cp_async16(smem_u + so + (uint32_t)((AW + lrow[j] * LDTW + lch[j] * 4) * 4),
                           Bb + (size_t)lrow[j] * HK + k0 + lch[j] * 8);
            }
        }
        asm volatile("cp.async.commit_group;" ::: "memory");

        // Complete stage cur's group; then barrier for cross-thread visibility
        asm volatile("cp.async.wait_group 1;" ::: "memory");
        __syncthreads();

        const uint32_t* As = smem + cur * STGW;
        const uint32_t* Bs = As + AW;

        // Fragment load helper for k-group kg into buffer slot b
        #define LOAD_FRAGS(bslot, kg_) do {                                              \
            const int kb_ = (kg_) * 8;                                                   \
            _Pragma("unroll")                                                            \
            for (int mf = 0; mf < 4; mf++) {                                             \
                const int rb = warpM * 64 + mf * 16 + g;                                 \
                const uint2 lo = *reinterpret_cast<const uint2*>(&As[rb * LDTW + kb_ + 2 * t4]);       \
                const uint2 hi = *reinterpret_cast<const uint2*>(&As[(rb + 8) * LDTW + kb_ + 2 * t4]); \
                af[bslot][mf][0] = lo.x; af[bslot][mf][1] = hi.x;                        \
                af[bslot][mf][2] = lo.y; af[bslot][mf][3] = hi.y;                        \
            }                                                                            \
            _Pragma("unroll")                                                            \
            for (int nfr = 0; nfr < 8; nfr++) {                                          \
                const int nb = warpN * 64 + nfr * 8 + g;                                 \
                const uint2 bb = *reinterpret_cast<const uint2*>(&Bs[nb * LDTW + kb_ + 2 * t4]);       \
                bf[bslot][nfr][0] = bb.x; bf[bslot][nfr][1] = bb.y;                      \
            }                                                                            \
        } while (0)

        LOAD_FRAGS(0, 0);
        #pragma unroll
        for (int kg = 0; kg < HBK / 16; kg++) {     // 4 k16-steps
            const int cb = kg & 1;
            if (kg + 1 < HBK / 16)
                LOAD_FRAGS((kg + 1) & 1, kg + 1);   // prefetch under MMAs
            #pragma unroll
            for (int mf = 0; mf < 4; mf++)
                #pragma unroll
                for (int nfr = 0; nfr < 8; nfr++)
                    mma_f16(acc[mf][nfr],
                            af[cb][mf][0], af[cb][mf][1], af[cb][mf][2], af[cb][mf][3],
                            bf[cb][nfr][0], bf[cb][nfr][1]);
        }
        #undef LOAD_FRAGS
    }

    // Epilogue
    const int m0 = blockIdx.y * 128 + warpM * 64;
    const int n0 = blockIdx.x * 128 + warpN * 64;
    if (F16OUT) {
        __half2* C = reinterpret_cast<__half2*>(Cv);
        #pragma unroll
        for (int mf = 0; mf < 4; mf++) {
            const int r0 = m0 + mf * 16 + g;
            #pragma unroll
            for (int nfr = 0; nfr < 8; nfr++) {
                const int c0 = n0 + nfr * 8 + t4 * 2;   // even
                C[((size_t)r0 * N + c0) >> 1] =
                    __floats2half2_rn(acc[mf][nfr][0], acc[mf][nfr][1]);
                C[((size_t)(r0 + 8) * N + c0) >> 1] =
                    __floats2half2_rn(acc[mf][nfr][2], acc[mf][nfr][3]);
            }
        }
    } else {
        float* C = reinterpret_cast<float*>(Cv);
        #pragma unroll
        for (int mf = 0; mf < 4; mf++) {
            const int r0 = m0 + mf * 16 + g;
            #pragma unroll
            for (int nfr = 0; nfr < 8; nfr++) {
                const int c0 = n0 + nfr * 8 + t4 * 2;
                *reinterpret_cast<float2*>(C + (size_t)r0 * N + c0) =
                    make_float2(acc[mf][nfr][0], acc[mf][nfr][1]);
                *reinterpret_cast<float2*>(C + (size_t)(r0 + 8) * N + c0) =
                    make_float2(acc[mf][nfr][2], acc[mf][nfr][3]);
            }
        }
    }
}

// ---------------------------------------------------------------------------
// Attention: one block per (n, h); 16-frame causal attention with RoPE.
// Reads fp16 qkv (natural layout); writes fp16 pair-permuted attn output.
// ---------------------------------------------------------------------------
__global__ void __launch_bounds__(64) attn_kernel()
{
    const int nh = blockIdx.x;
    const int n  = nh >> 4;
    const int h  = nh & 15;
    const int b  = n >> 10;
    const int s  = n & 1023;
    const int d  = threadIdx.x;

    __shared__ float qs[FRAMES][HDIM + 1];
    __shared__ float ks[FRAMES][HDIM + 1];
    __shared__ float vs[FRAMES][HDIM];
    __shared__ float ssm[FRAMES][FRAMES];

    const int col = h * HDIM + d;
    #pragma unroll
    for (int t = 0; t < FRAMES; t++) {
        const size_t row = (size_t)((b * FRAMES + t) * SPATIAL + s) * QKV_N;
        qs[t][d] = __half2float(g_qkv_h[row + col]);
        ks[t][d] = __half2float(g_qkv_h[row + HIDDEN + col]);
        vs[t][d] = __half2float(g_qkv_h[row + 2 * HIDDEN + col]);
    }
    __syncthreads();

    const int i = d & 31;
    const float inv_freq = expf(-(float)(2 * i) * (9.210340371976184f / 64.0f));
    float qr[FRAMES], kr[FRAMES];
    #pragma unroll
    for (int t = 0; t < FRAMES; t++) {
        const float fr = (float)t * inv_freq;
        const float c  = cosf(fr);
        const float sn = sinf(fr);
        const float rotq = (d < 32) ? -qs[t][d + 32] : qs[t][d - 32];
        const float rotk = (d < 32) ? -ks[t][d + 32] : ks[t][d - 32];
        qr[t] = qs[t][d] * c + rotq * sn;
        kr[t] = ks[t][d] * c + rotk * sn;
    }
    __syncthreads();
    #pragma unroll
    for (int t = 0; t < FRAMES; t++) { qs[t][d] = qr[t]; ks[t][d] = kr[t]; }
    __syncthreads();

    #pragma unroll
    for (int idx = d; idx < FRAMES * FRAMES; idx += 64) {
        const int tq = idx >> 4;
        const int tk = idx & 15;
        float a;
        if (tk <= tq) {
            a = 0.f;
            #pragma unroll
            for (int e = 0; e < HDIM; e++) a += qs[tq][e] * ks[tk][e];
            a *= 0.125f;
        } else {
            a = -INFINITY;
        }
        ssm[tq][tk] = a;
    }
    __syncthreads();

    if (d < FRAMES) {
        float m = ssm[d][0];
        for (int k = 1; k <= d; k++) m = fmaxf(m, ssm[d][k]);
        float sum = 0.f;
        for (int k = 0; k <= d; k++) {
            const float e = expf(ssm[d][k] - m);
            ssm[d][k] = e;
            sum += e;
        }
        const float r = 1.0f / sum;
        for (int k = 0; k <= d; k++) ssm[d][k] *= r;
        for (int k = d + 1; k < FRAMES; k++) ssm[d][k] = 0.f;
    }
    __syncthreads();

    // Permuted fp16 destination: element index within head = pair-permuted d
    const int g16  = d >> 4;
    const int pl   = (d >> 1) & 7;
    const int dp   = h * HDIM + g16 * 16 + pslot(pl) * 2 + (d & 1);
    #pragma unroll
    for (int t = 0; t < FRAMES; t++) {
        float a = 0.f;
        #pragma unroll
        for (int k = 0; k < FRAMES; k++) a += ssm[t][k] * vs[k][d];
        g_attn_h[(size_t)((b * FRAMES + t) * SPATIAL + s) * HIDDEN + dp] = __float2half_rn(a);
    }
}

// ---------------------------------------------------------------------------
// Launch
// ---------------------------------------------------------------------------
extern "C" void kernel_launch(void* const* d_in, const int* in_sizes, int n_in,
                              void* d_out, int out_size)
{
    const float* x      = (const float*)d_in[0];
    const float* w_qkv  = (const float*)d_in[1];
    const float* w_out  = (const float*)d_in[2];
    const float* gamma  = (const float*)d_in[3];
    const float* beta   = (const float*)d_in[4];

    __half* xn_p;   cudaGetSymbolAddress((void**)&xn_p,   g_xn_h);
    __half* qkv_p;  cudaGetSymbolAddress((void**)&qkv_p,  g_qkv_h);
    __half* attn_p; cudaGetSymbolAddress((void**)&attn_p, g_attn_h);
    __half* wqkv_p; cudaGetSymbolAddress((void**)&wqkv_p, g_wqkv_h);
    __half* wout_p; cudaGetSymbolAddress((void**)&wout_p, g_wout_h);

    cudaFuncSetAttribute(gemm_h<true>,  cudaFuncAttributeMaxDynamicSharedMemorySize,
                         GEMM_SMEM_BYTES);
    cudaFuncSetAttribute(gemm_h<false>, cudaFuncAttributeMaxDynamicSharedMemorySize,
                         GEMM_SMEM_BYTES);

    // 0) Round+permute weights to fp16 (tiny)
    round_perm_w_h<<<QKV_N, 256>>>(w_qkv, (__half2*)wqkv_p);
    round_perm_w_h<<<HIDDEN, 256>>>(w_out, (__half2*)wout_p);

    // 1) LayerNorm -> fp16 permuted
    ln_kernel<<<NTOK, 256>>>(x, gamma, beta);

    // 2) QKV projection [fp16 m16n8k16 mma, frag double-buffered] -> fp16 qkv
    gemm_h<true><<<dim3(QKV_N / 128, NTOK / 128), 128, GEMM_SMEM_BYTES>>>(
        xn_p, wqkv_p, qkv_p, QKV_N);

    // 3) Attention (RoPE + causal softmax + PV) -> fp16 permuted
    attn_kernel<<<NTOK, 64>>>();

    // 4) Output projection -> d_out (fp32)
    gemm_h<false><<<dim3(HIDDEN / 128, NTOK / 128), 128, GEMM_SMEM_BYTES>>>(
        attn_p, wout_p, d_out, HIDDEN);
}

// round 15
// speedup vs baseline: 1.5617x; 1.5617x over previous
#include <cuda_runtime.h>
#include <cuda_fp16.h>
#include <math.h>
#include <stdint.h>

// Problem constants (hardcoded from reference setup_inputs)
#define BATCH   2
#define FRAMES  16
#define SPATIAL 1024            // height*width = 32*32
#define HIDDEN  1024
#define NHEADS  16
#define HDIM    64
#define NTOK    (BATCH*FRAMES*SPATIAL)   // 32768
#define QKV_N   (3*HIDDEN)               // 3072
#define LN_EPS  1e-5f

// Scratch buffers (device globals; no runtime allocation allowed)
__device__ __half g_xn_h[(size_t)NTOK * HIDDEN];      // 64 MB  (fp16, pair-permuted)
__device__ __half g_qkv_h[(size_t)NTOK * QKV_N];      // 201 MB (fp16, natural layout)
__device__ __half g_attn_h[(size_t)NTOK * HIDDEN];    // 64 MB  (fp16, pair-permuted)
__device__ __half g_wqkv_h[(size_t)QKV_N * HIDDEN];   // 6 MB   (fp16, pair-permuted)
__device__ __half g_wout_h[(size_t)HIDDEN * HIDDEN];  // 2 MB   (fp16, pair-permuted)

// Pair-level K-permutation: within each 16-element k-group (8 fp16 pairs),
// pair p -> slot (p<4 ? 2p : 2(p-4)+1). Fragment pairs (t4, t4+4) land adjacent.
__device__ __forceinline__ int pslot(int p) {   // p in 0..7
    return (p < 4) ? (2 * p) : (2 * (p - 4) + 1);
}

__device__ __forceinline__ void cp_async16(uint32_t saddr, const void* gaddr) {
    asm volatile("cp.async.cg.shared.global [%0], [%1], 16;" :: "r"(saddr), "l"(gaddr));
}

// ---------------------------------------------------------------------------
// Weight round+permute: fp32 row-major [rows,1024] -> fp16 pair-permuted.
// ---------------------------------------------------------------------------
__global__ void __launch_bounds__(256) round_perm_w_h(const float* __restrict__ w,
                                                      __half2* __restrict__ out)
{
    const int row = blockIdx.x;
    const int tid = threadIdx.x;
    const float4 v = reinterpret_cast<const float4*>(w + (size_t)row * HIDDEN)[tid];
    const int g16  = tid >> 2;                 // 16-elem group index (8 half2 words)
    const int pl   = 2 * (tid & 3);            // first pair index within group
    __half2* obase = out + (size_t)row * (HIDDEN / 2) + g16 * 8;
    obase[pslot(pl)]     = __floats2half2_rn(v.x, v.y);
    obase[pslot(pl + 1)] = __floats2half2_rn(v.z, v.w);
}

// ---------------------------------------------------------------------------
// LayerNorm: one block per token; output fp16 pair-permuted
// ---------------------------------------------------------------------------
__global__ void __launch_bounds__(256) ln_kernel(const float* __restrict__ x,
                                                 const float* __restrict__ gamma,
                                                 const float* __restrict__ beta)
{
    const int tok = blockIdx.x;
    const int tid = threadIdx.x;
    const float4* xr = reinterpret_cast<const float4*>(x + (size_t)tok * HIDDEN);
    float4 v = xr[tid];

    float s  = v.x + v.y + v.z + v.w;
    float ss = v.x*v.x + v.y*v.y + v.z*v.z + v.w*v.w;

    #pragma unroll
    for (int o = 16; o > 0; o >>= 1) {
        s  += __shfl_xor_sync(0xffffffffu, s,  o);
        ss += __shfl_xor_sync(0xffffffffu, ss, o);
    }
    __shared__ float red_s[8], red_ss[8];
    const int warp = tid >> 5, lane = tid & 31;
    if (lane == 0) { red_s[warp] = s; red_ss[warp] = ss; }
    __syncthreads();
    float fs = 0.f, fss = 0.f;
    #pragma unroll
    for (int i = 0; i < 8; i++) { fs += red_s[i]; fss += red_ss[i]; }

    const float mean = fs * (1.0f / HIDDEN);
    const float var  = fss * (1.0f / HIDDEN) - mean * mean;
    const float inv  = rsqrtf(var + LN_EPS);

    const float4 gm = reinterpret_cast<const float4*>(gamma)[tid];
    const float4 bt = reinterpret_cast<const float4*>(beta)[tid];
    const float o0 = (v.x - mean) * inv * gm.x + bt.x;
    const float o1 = (v.y - mean) * inv * gm.y + bt.y;
    const float o2 = (v.z - mean) * inv * gm.z + bt.z;
    const float o3 = (v.w - mean) * inv * gm.w + bt.w;

    const int g16 = tid >> 2;
    const int pl  = 2 * (tid & 3);
    __half2* obase = reinterpret_cast<__half2*>(g_xn_h) + (size_t)tok * (HIDDEN / 2) + g16 * 8;
    obase[pslot(pl)]     = __floats2half2_rn(o0, o1);
    obase[pslot(pl + 1)] = __floats2half2_rn(o2, o3);
}

// ---------------------------------------------------------------------------
// FP16 mma.sync GEMM (NT), K=1024: C[m][n] = sum_k A[m][k]*B[n][k]
// A, B fp16 pair-permuted. CTA tile 128x128, BK=64 fp16, 128 threads =
// 4 warps (2Mx2N), warp tile 64x64 of m16n8k16. 2-stage cp.async pipeline.
// (R13 version — fastest proven GEMM; frag double-buffering regressed.)
// F16OUT: C stored as __half2 (QKV path); else fp32 (final output).
// ---------------------------------------------------------------------------
#define HK      1024
#define HBK     64
#define HNIT    (HK / HBK)      // 16
#define LDTW    40              // 4-byte words per smem row
#define AW      (128 * LDTW)    // words per matrix per stage (5120)
#define STGW    (2 * AW)        // words per stage (A+B)
#define GEMM_SMEM_BYTES (2 * STGW * 4)   // 81920

__device__ __forceinline__ void mma_f16(float c[4],
                                        uint32_t a0, uint32_t a1, uint32_t a2, uint32_t a3,
                                        uint32_t b0, uint32_t b1)
{
    asm volatile(
        "mma.sync.aligned.m16n8k16.row.col.f32.f16.f16.f32 "
        "{%0,%1,%2,%3}, {%4,%5,%6,%7}, {%8,%9}, {%0,%1,%2,%3};"
        : "+f"(c[0]), "+f"(c[1]), "+f"(c[2]), "+f"(c[3])
        : "r"(a0), "r"(a1), "r"(a2), "r"(a3), "r"(b0), "r"(b1));
}

template<bool F16OUT>
__global__ void __launch_bounds__(128, 2)
gemm_h(const __half* __restrict__ A, const __half* __restrict__ B,
       void* __restrict__ Cv, int N)
{
    extern __shared__ uint32_t smem[];   // [2][STGW] words

    const int tid  = threadIdx.x;
    const int wid  = tid >> 5;
    const int lane = tid & 31;
    const int g    = lane >> 2;
    const int t4   = lane & 3;
    const int warpM = wid & 1;        // 0..1 -> 64 rows
    const int warpN = wid >> 1;       // 0..1 -> 64 cols

    const __half* Ab = A + (size_t)blockIdx.y * 128 * HK;
    const __half* Bb = B + (size_t)blockIdx.x * 128 * HK;

    const uint32_t smem_u = (uint32_t)__cvta_generic_to_shared(smem);

    // Loader mapping: per matrix per stage 128 rows x 8 chunks(16B) = 1024;
    // 128 threads -> 8 chunks/thread/matrix.
    int lrow[8], lch[8];
    #pragma unroll
    for (int j = 0; j < 8; j++) {
        const int lin = tid + j * 128;
        lrow[j] = lin >> 3;
        lch[j]  = lin & 7;
    }

    float acc[4][8][4];
    #pragma unroll
    for (int i = 0; i < 4; i++)
        #pragma unroll
        for (int j = 0; j < 8; j++)
            #pragma unroll
            for (int r = 0; r < 4; r++) acc[i][j][r] = 0.f;

    // Prologue: fill stage 0 with tile 0
    #pragma unroll
    for (int j = 0; j < 8; j++) {
        cp_async16(smem_u + (uint32_t)((lrow[j] * LDTW + lch[j] * 4) * 4),
                   Ab + (size_t)lrow[j] * HK + lch[j] * 8);
        cp_async16(smem_u + (uint32_t)((AW + lrow[j] * LDTW + lch[j] * 4) * 4),
                   Bb + (size_t)lrow[j] * HK + lch[j] * 8);
    }
    asm volatile("cp.async.commit_group;" ::: "memory");

    #pragma unroll 1
    for (int it = 0; it < HNIT; it++) {
        const int cur = it & 1;
        const int nxt = cur ^ 1;

        // All warps finished computing stage nxt's previous contents
        __syncthreads();

        // Fill stage nxt with tile it+1 (overlaps MMAs below)
        if (it + 1 < HNIT) {
            const int k0 = (it + 1) * HBK;
            const uint32_t so = (uint32_t)(nxt * STGW) * 4u;
            #pragma unroll
            for (int j = 0; j < 8; j++) {
                cp_async16(smem_u + so + (uint32_t)((lrow[j] * LDTW + lch[j] * 4) * 4),
                           Ab + (size_t)lrow[j] * HK + k0 + lch[j] * 8);
                cp_async16(smem_u + so + (uint32_t)((AW + lrow[j] * LDTW + lch[j] * 4) * 4),
                           Bb + (size_t)lrow[j] * HK + k0 + lch[j] * 8);
            }
        }
        asm volatile("cp.async.commit_group;" ::: "memory");

        // Complete stage cur's group; then barrier for cross-thread visibility
        asm volatile("cp.async.wait_group 1;" ::: "memory");
        __syncthreads();

        const uint32_t* As = smem + cur * STGW;
        const uint32_t* Bs = As + AW;
        #pragma unroll
        for (int kg = 0; kg < HBK / 16; kg++) {     // 4 k16-steps
            const int kb = kg * 8;                  // word base of k-group
            uint32_t af[4][4];
            #pragma unroll
            for (int mf = 0; mf < 4; mf++) {
                const int rb = warpM * 64 + mf * 16 + g;
                const uint2 lo = *reinterpret_cast<const uint2*>(&As[rb * LDTW + kb + 2 * t4]);
                const uint2 hi = *reinterpret_cast<const uint2*>(&As[(rb + 8) * LDTW + kb + 2 * t4]);
                af[mf][0] = lo.x;
                af[mf][1] = hi.x;
                af[mf][2] = lo.y;
                af[mf][3] = hi.y;
            }
            uint32_t bf[8][2];
            #pragma unroll
            for (int nfr = 0; nfr < 8; nfr++) {
                const int nb = warpN * 64 + nfr * 8 + g;
                const uint2 bb = *reinterpret_cast<const uint2*>(&Bs[nb * LDTW + kb + 2 * t4]);
                bf[nfr][0] = bb.x;
                bf[nfr][1] = bb.y;
            }
            #pragma unroll
            for (int mf = 0; mf < 4; mf++)
                #pragma unroll
                for (int nfr = 0; nfr < 8; nfr++)
                    mma_f16(acc[mf][nfr], af[mf][0], af[mf][1], af[mf][2], af[mf][3],
                            bf[nfr][0], bf[nfr][1]);
        }
    }

    // Epilogue
    const int m0 = blockIdx.y * 128 + warpM * 64;
    const int n0 = blockIdx.x * 128 + warpN * 64;
    if (F16OUT) {
        __half2* C = reinterpret_cast<__half2*>(Cv);
        #pragma unroll
        for (int mf = 0; mf < 4; mf++) {
            const int r0 = m0 + mf * 16 + g;
            #pragma unroll
            for (int nfr = 0; nfr < 8; nfr++) {
                const int c0 = n0 + nfr * 8 + t4 * 2;   // even
                C[((size_t)r0 * N + c0) >> 1] =
                    __floats2half2_rn(acc[mf][nfr][0], acc[mf][nfr][1]);
                C[((size_t)(r0 + 8) * N + c0) >> 1] =
                    __floats2half2_rn(acc[mf][nfr][2], acc[mf][nfr][3]);
            }
        }
    } else {
        float* C = reinterpret_cast<float*>(Cv);
        #pragma unroll
        for (int mf = 0; mf < 4; mf++) {
            const int r0 = m0 + mf * 16 + g;
            #pragma unroll
            for (int nfr = 0; nfr < 8; nfr++) {
                const int c0 = n0 + nfr * 8 + t4 * 2;
                *reinterpret_cast<float2*>(C + (size_t)r0 * N + c0) =
                    make_float2(acc[mf][nfr][0], acc[mf][nfr][1]);
                *reinterpret_cast<float2*>(C + (size_t)(r0 + 8) * N + c0) =
                    make_float2(acc[mf][nfr][2], acc[mf][nfr][3]);
            }
        }
    }
}

// ---------------------------------------------------------------------------
// Attention: one block per (n, h); 16-frame causal attention with RoPE.
// Reads fp16 qkv via coalesced __half2 loads; writes fp16 pair-permuted output.
// ---------------------------------------------------------------------------
__global__ void __launch_bounds__(64) attn_kernel()
{
    const int nh = blockIdx.x;
    const int n  = nh >> 4;
    const int h  = nh & 15;
    const int b  = n >> 10;
    const int s  = n & 1023;
    const int d  = threadIdx.x;

    __shared__ float qs[FRAMES][HDIM + 1];
    __shared__ float ks[FRAMES][HDIM + 1];
    __shared__ float vs[FRAMES][HDIM];
    __shared__ float ssm[FRAMES][FRAMES];

    // Vectorized loads: threads 0-31 fetch q+v half2 pairs, threads 32-63 fetch k.
    const __half2* qkv2 = reinterpret_cast<const __half2*>(g_qkv_h);
    #pragma unroll
    for (int t = 0; t < FRAMES; t++) {
        const size_t r2 = ((size_t)((b * FRAMES + t) * SPATIAL + s) * QKV_N
                           + h * HDIM) >> 1;
        if (d < 32) {
            const float2 fq = __half22float2(qkv2[r2 + d]);              // q
            qs[t][2 * d]     = fq.x;
            qs[t][2 * d + 1] = fq.y;
            const float2 fv = __half22float2(qkv2[r2 + 1024 + d]);       // v (+2*HIDDEN halves)
            vs[t][2 * d]     = fv.x;
            vs[t][2 * d + 1] = fv.y;
        } else {
            const int j = d - 32;
            const float2 fk = __half22float2(qkv2[r2 + 512 + j]);        // k (+HIDDEN halves)
            ks[t][2 * j]     = fk.x;
            ks[t][2 * j + 1] = fk.y;
        }
    }
    __syncthreads();

    const int i = d & 31;
    const float inv_freq = expf(-(float)(2 * i) * (9.210340371976184f / 64.0f));
    float qr[FRAMES], kr[FRAMES];
    #pragma unroll
    for (int t = 0; t < FRAMES; t++) {
        const float fr = (float)t * inv_freq;
        const float c  = cosf(fr);
        const float sn = sinf(fr);
        const float rotq = (d < 32) ? -qs[t][d + 32] : qs[t][d - 32];
        const float rotk = (d < 32) ? -ks[t][d + 32] : ks[t][d - 32];
        qr[t] = qs[t][d] * c + rotq * sn;
        kr[t] = ks[t][d] * c + rotk * sn;
    }
    __syncthreads();
    #pragma unroll
    for (int t = 0; t < FRAMES; t++) { qs[t][d] = qr[t]; ks[t][d] = kr[t]; }
    __syncthreads();

    #pragma unroll
    for (int idx = d; idx < FRAMES * FRAMES; idx += 64) {
        const int tq = idx >> 4;
        const int tk = idx & 15;
        float a;
        if (tk <= tq) {
            a = 0.f;
            #pragma unroll
            for (int e = 0; e < HDIM; e++) a += qs[tq][e] * ks[tk][e];
            a *= 0.125f;
        } else {
            a = -INFINITY;
        }
        ssm[tq][tk] = a;
    }
    __syncthreads();

    if (d < FRAMES) {
        float m = ssm[d][0];
        for (int k = 1; k <= d; k++) m = fmaxf(m, ssm[d][k]);
        float sum = 0.f;
        for (int k = 0; k <= d; k++) {
            const float e = expf(ssm[d][k] - m);
            ssm[d][k] = e;
            sum += e;
        }
        const float r = 1.0f / sum;
        for (int k = 0; k <= d; k++) ssm[d][k] *= r;
        for (int k = d + 1; k < FRAMES; k++) ssm[d][k] = 0.f;
    }
    __syncthreads();

    // Permuted fp16 destination: element index within head = pair-permuted d
    const int g16  = d >> 4;
    const int pl   = (d >> 1) & 7;
    const int dp   = h * HDIM + g16 * 16 + pslot(pl) * 2 + (d & 1);
    #pragma unroll
    for (int t = 0; t < FRAMES; t++) {
        float a = 0.f;
        #pragma unroll
        for (int k = 0; k < FRAMES; k++) a += ssm[t][k] * vs[k][d];
        g_attn_h[(size_t)((b * FRAMES + t) * SPATIAL + s) * HIDDEN + dp] = __float2half_rn(a);
    }
}

// ---------------------------------------------------------------------------
// Launch
// ---------------------------------------------------------------------------
extern "C" void kernel_launch(void* const* d_in, const int* in_sizes, int n_in,
                              void* d_out, int out_size)
{
    const float* x      = (const float*)d_in[0];
    const float* w_qkv  = (const float*)d_in[1];
    const float* w_out  = (const float*)d_in[2];
    const float* gamma  = (const float*)d_in[3];
    const float* beta   = (const float*)d_in[4];

    __half* xn_p;   cudaGetSymbolAddress((void**)&xn_p,   g_xn_h);
    __half* qkv_p;  cudaGetSymbolAddress((void**)&qkv_p,  g_qkv_h);
    __half* attn_p; cudaGetSymbolAddress((void**)&attn_p, g_attn_h);
    __half* wqkv_p; cudaGetSymbolAddress((void**)&wqkv_p, g_wqkv_h);
    __half* wout_p; cudaGetSymbolAddress((void**)&wout_p, g_wout_h);

    cudaFuncSetAttribute(gemm_h<true>,  cudaFuncAttributeMaxDynamicSharedMemorySize,
                         GEMM_SMEM_BYTES);
    cudaFuncSetAttribute(gemm_h<false>, cudaFuncAttributeMaxDynamicSharedMemorySize,
                         GEMM_SMEM_BYTES);

    // 0) Round+permute weights to fp16 (tiny)
    round_perm_w_h<<<QKV_N, 256>>>(w_qkv, (__half2*)wqkv_p);
    round_perm_w_h<<<HIDDEN, 256>>>(w_out, (__half2*)wout_p);

    // 1) LayerNorm -> fp16 permuted
    ln_kernel<<<NTOK, 256>>>(x, gamma, beta);

    // 2) QKV projection [fp16 m16n8k16 mma] -> fp16 qkv
    gemm_h<true><<<dim3(QKV_N / 128, NTOK / 128), 128, GEMM_SMEM_BYTES>>>(
        xn_p, wqkv_p, qkv_p, QKV_N);

    // 3) Attention (RoPE + causal softmax + PV) -> fp16 permuted
    attn_kernel<<<NTOK, 64>>>();

    // 4) Output projection -> d_out (fp32)
    gemm_h<false><<<dim3(HIDDEN / 128, NTOK / 128), 128, GEMM_SMEM_BYTES>>>(
        attn_p, wout_p, d_out, HIDDEN);
}

// round 16
// speedup vs baseline: 1.9561x; 1.2525x over previous
#include <cuda_runtime.h>
#include <cuda_fp16.h>
#include <math.h>
#include <stdint.h>

// Problem constants (hardcoded from reference setup_inputs)
#define BATCH   2
#define FRAMES  16
#define SPATIAL 1024            // height*width = 32*32
#define HIDDEN  1024
#define NHEADS  16
#define HDIM    64
#define NTOK    (BATCH*FRAMES*SPATIAL)   // 32768
#define QKV_N   (3*HIDDEN)               // 3072
#define LN_EPS  1e-5f

// Scratch buffers (device globals; no runtime allocation allowed)
__device__ __half g_xn_h[(size_t)NTOK * HIDDEN];      // 64 MB  (fp16, pair-permuted)
__device__ __half g_qkv_h[(size_t)NTOK * QKV_N];      // 201 MB (fp16, natural layout)
__device__ __half g_attn_h[(size_t)NTOK * HIDDEN];    // 64 MB  (fp16, pair-permuted)
__device__ __half g_wqkv_h[(size_t)QKV_N * HIDDEN];   // 6 MB   (fp16, pair-permuted)
__device__ __half g_wout_h[(size_t)HIDDEN * HIDDEN];  // 2 MB   (fp16, pair-permuted)
__device__ float  g_rope_cos[FRAMES * 32];            // RoPE tables
__device__ float  g_rope_sin[FRAMES * 32];

// Pair-level K-permutation: within each 16-element k-group (8 fp16 pairs),
// pair p -> slot (p<4 ? 2p : 2(p-4)+1). Fragment pairs (t4, t4+4) land adjacent.
__device__ __forceinline__ int pslot(int p) {   // p in 0..7
    return (p < 4) ? (2 * p) : (2 * (p - 4) + 1);
}

__device__ __forceinline__ void cp_async16(uint32_t saddr, const void* gaddr) {
    asm volatile("cp.async.cg.shared.global [%0], [%1], 16;" :: "r"(saddr), "l"(gaddr));
}

// ---------------------------------------------------------------------------
// RoPE table init: cos/sin(t * 10000^(-2i/64)) for t in 0..15, i in 0..31
// ---------------------------------------------------------------------------
__global__ void rope_init()
{
    const int tid = threadIdx.x;      // 0..511
    const int t = tid >> 5, i = tid & 31;
    const float inv_freq = expf(-(float)(2 * i) * (9.210340371976184f / 64.0f));
    const float fr = (float)t * inv_freq;
    g_rope_cos[tid] = cosf(fr);
    g_rope_sin[tid] = sinf(fr);
}

// ---------------------------------------------------------------------------
// Weight round+permute: fp32 row-major [rows,1024] -> fp16 pair-permuted.
// ---------------------------------------------------------------------------
__global__ void __launch_bounds__(256) round_perm_w_h(const float* __restrict__ w,
                                                      __half2* __restrict__ out)
{
    const int row = blockIdx.x;
    const int tid = threadIdx.x;
    const float4 v = reinterpret_cast<const float4*>(w + (size_t)row * HIDDEN)[tid];
    const int g16  = tid >> 2;                 // 16-elem group index (8 half2 words)
    const int pl   = 2 * (tid & 3);            // first pair index within group
    __half2* obase = out + (size_t)row * (HIDDEN / 2) + g16 * 8;
    obase[pslot(pl)]     = __floats2half2_rn(v.x, v.y);
    obase[pslot(pl + 1)] = __floats2half2_rn(v.z, v.w);
}

// ---------------------------------------------------------------------------
// LayerNorm: one block per token; output fp16 pair-permuted
// ---------------------------------------------------------------------------
__global__ void __launch_bounds__(256) ln_kernel(const float* __restrict__ x,
                                                 const float* __restrict__ gamma,
                                                 const float* __restrict__ beta)
{
    const int tok = blockIdx.x;
    const int tid = threadIdx.x;
    const float4* xr = reinterpret_cast<const float4*>(x + (size_t)tok * HIDDEN);
    float4 v = xr[tid];

    float s  = v.x + v.y + v.z + v.w;
    float ss = v.x*v.x + v.y*v.y + v.z*v.z + v.w*v.w;

    #pragma unroll
    for (int o = 16; o > 0; o >>= 1) {
        s  += __shfl_xor_sync(0xffffffffu, s,  o);
        ss += __shfl_xor_sync(0xffffffffu, ss, o);
    }
    __shared__ float red_s[8], red_ss[8];
    const int warp = tid >> 5, lane = tid & 31;
    if (lane == 0) { red_s[warp] = s; red_ss[warp] = ss; }
    __syncthreads();
    float fs = 0.f, fss = 0.f;
    #pragma unroll
    for (int i = 0; i < 8; i++) { fs += red_s[i]; fss += red_ss[i]; }

    const float mean = fs * (1.0f / HIDDEN);
    const float var  = fss * (1.0f / HIDDEN) - mean * mean;
    const float inv  = rsqrtf(var + LN_EPS);

    const float4 gm = reinterpret_cast<const float4*>(gamma)[tid];
    const float4 bt = reinterpret_cast<const float4*>(beta)[tid];
    const float o0 = (v.x - mean) * inv * gm.x + bt.x;
    const float o1 = (v.y - mean) * inv * gm.y + bt.y;
    const float o2 = (v.z - mean) * inv * gm.z + bt.z;
    const float o3 = (v.w - mean) * inv * gm.w + bt.w;

    const int g16 = tid >> 2;
    const int pl  = 2 * (tid & 3);
    __half2* obase = reinterpret_cast<__half2*>(g_xn_h) + (size_t)tok * (HIDDEN / 2) + g16 * 8;
    obase[pslot(pl)]     = __floats2half2_rn(o0, o1);
    obase[pslot(pl + 1)] = __floats2half2_rn(o2, o3);
}

// ---------------------------------------------------------------------------
// FP16 mma.sync helpers
// ---------------------------------------------------------------------------
__device__ __forceinline__ void mma_f16(float c[4],
                                        uint32_t a0, uint32_t a1, uint32_t a2, uint32_t a3,
                                        uint32_t b0, uint32_t b1)
{
    asm volatile(
        "mma.sync.aligned.m16n8k16.row.col.f32.f16.f16.f32 "
        "{%0,%1,%2,%3}, {%4,%5,%6,%7}, {%8,%9}, {%0,%1,%2,%3};"
        : "+f"(c[0]), "+f"(c[1]), "+f"(c[2]), "+f"(c[3])
        : "r"(a0), "r"(a1), "r"(a2), "r"(a3), "r"(b0), "r"(b1));
}

// ---------------------------------------------------------------------------
// FP16 mma.sync GEMM (NT), K=1024: C[m][n] = sum_k A[m][k]*B[n][k]
// (R13/R15 version — fastest proven GEMM.)
// ---------------------------------------------------------------------------
#define HK      1024
#define HBK     64
#define HNIT    (HK / HBK)      // 16
#define LDTW    40              // 4-byte words per smem row
#define AW      (128 * LDTW)    // words per matrix per stage (5120)
#define STGW    (2 * AW)        // words per stage (A+B)
#define GEMM_SMEM_BYTES (2 * STGW * 4)   // 81920

template<bool F16OUT>
__global__ void __launch_bounds__(128, 2)
gemm_h(const __half* __restrict__ A, const __half* __restrict__ B,
       void* __restrict__ Cv, int N)
{
    extern __shared__ uint32_t smem[];   // [2][STGW] words

    const int tid  = threadIdx.x;
    const int wid  = tid >> 5;
    const int lane = tid & 31;
    const int g    = lane >> 2;
    const int t4   = lane & 3;
    const int warpM = wid & 1;        // 0..1 -> 64 rows
    const int warpN = wid >> 1;       // 0..1 -> 64 cols

    const __half* Ab = A + (size_t)blockIdx.y * 128 * HK;
    const __half* Bb = B + (size_t)blockIdx.x * 128 * HK;

    const uint32_t smem_u = (uint32_t)__cvta_generic_to_shared(smem);

    int lrow[8], lch[8];
    #pragma unroll
    for (int j = 0; j < 8; j++) {
        const int lin = tid + j * 128;
        lrow[j] = lin >> 3;
        lch[j]  = lin & 7;
    }

    float acc[4][8][4];
    #pragma unroll
    for (int i = 0; i < 4; i++)
        #pragma unroll
        for (int j = 0; j < 8; j++)
            #pragma unroll
            for (int r = 0; r < 4; r++) acc[i][j][r] = 0.f;

    #pragma unroll
    for (int j = 0; j < 8; j++) {
        cp_async16(smem_u + (uint32_t)((lrow[j] * LDTW + lch[j] * 4) * 4),
                   Ab + (size_t)lrow[j] * HK + lch[j] * 8);
        cp_async16(smem_u + (uint32_t)((AW + lrow[j] * LDTW + lch[j] * 4) * 4),
                   Bb + (size_t)lrow[j] * HK + lch[j] * 8);
    }
    asm volatile("cp.async.commit_group;" ::: "memory");

    #pragma unroll 1
    for (int it = 0; it < HNIT; it++) {
        const int cur = it & 1;
        const int nxt = cur ^ 1;

        __syncthreads();

        if (it + 1 < HNIT) {
            const int k0 = (it + 1) * HBK;
            const uint32_t so = (uint32_t)(nxt * STGW) * 4u;
            #pragma unroll
            for (int j = 0; j < 8; j++) {
                cp_async16(smem_u + so + (uint32_t)((lrow[j] * LDTW + lch[j] * 4) * 4),
                           Ab + (size_t)lrow[j] * HK + k0 + lch[j] * 8);
                cp_async16(smem_u + so + (uint32_t)((AW + lrow[j] * LDTW + lch[j] * 4) * 4),
                           Bb + (size_t)lrow[j] * HK + k0 + lch[j] * 8);
            }
        }
        asm volatile("cp.async.commit_group;" ::: "memory");

        asm volatile("cp.async.wait_group 1;" ::: "memory");
        __syncthreads();

        const uint32_t* As = smem + cur * STGW;
        const uint32_t* Bs = As + AW;
        #pragma unroll
        for (int kg = 0; kg < HBK / 16; kg++) {
            const int kb = kg * 8;
            uint32_t af[4][4];
            #pragma unroll
            for (int mf = 0; mf < 4; mf++) {
                const int rb = warpM * 64 + mf * 16 + g;
                const uint2 lo = *reinterpret_cast<const uint2*>(&As[rb * LDTW + kb + 2 * t4]);
                const uint2 hi = *reinterpret_cast<const uint2*>(&As[(rb + 8) * LDTW + kb + 2 * t4]);
                af[mf][0] = lo.x;
                af[mf][1] = hi.x;
                af[mf][2] = lo.y;
                af[mf][3] = hi.y;
            }
            uint32_t bf[8][2];
            #pragma unroll
            for (int nfr = 0; nfr < 8; nfr++) {
                const int nb = warpN * 64 + nfr * 8 + g;
                const uint2 bb = *reinterpret_cast<const uint2*>(&Bs[nb * LDTW + kb + 2 * t4]);
                bf[nfr][0] = bb.x;
                bf[nfr][1] = bb.y;
            }
            #pragma unroll
            for (int mf = 0; mf < 4; mf++)
                #pragma unroll
                for (int nfr = 0; nfr < 8; nfr++)
                    mma_f16(acc[mf][nfr], af[mf][0], af[mf][1], af[mf][2], af[mf][3],
                            bf[nfr][0], bf[nfr][1]);
        }
    }

    const int m0 = blockIdx.y * 128 + warpM * 64;
    const int n0 = blockIdx.x * 128 + warpN * 64;
    if (F16OUT) {
        __half2* C = reinterpret_cast<__half2*>(Cv);
        #pragma unroll
        for (int mf = 0; mf < 4; mf++) {
            const int r0 = m0 + mf * 16 + g;
            #pragma unroll
            for (int nfr = 0; nfr < 8; nfr++) {
                const int c0 = n0 + nfr * 8 + t4 * 2;
                C[((size_t)r0 * N + c0) >> 1] =
                    __floats2half2_rn(acc[mf][nfr][0], acc[mf][nfr][1]);
                C[((size_t)(r0 + 8) * N + c0) >> 1] =
                    __floats2half2_rn(acc[mf][nfr][2], acc[mf][nfr][3]);
            }
        }
    } else {
        float* C = reinterpret_cast<float*>(Cv);
        #pragma unroll
        for (int mf = 0; mf < 4; mf++) {
            const int r0 = m0 + mf * 16 + g;
            #pragma unroll
            for (int nfr = 0; nfr < 8; nfr++) {
                const int c0 = n0 + nfr * 8 + t4 * 2;
                *reinterpret_cast<float2*>(C + (size_t)r0 * N + c0) =
                    make_float2(acc[mf][nfr][0], acc[mf][nfr][1]);
                *reinterpret_cast<float2*>(C + (size_t)(r0 + 8) * N + c0) =
                    make_float2(acc[mf][nfr][2], acc[mf][nfr][3]);
            }
        }
    }
}

// ---------------------------------------------------------------------------
// Tensor-core attention: ONE WARP per (n, h). 16-frame causal + RoPE.
// S(16x16) = Q K^T via 2x m16n8k16 per 16-k-chunk; register softmax with
// quad shuffles; P accumulators re-packed directly as A-fragments (FA trick);
// O(16x64) = P V via 8x m16n8k16. Natural-layout smem, 72-half row stride
// (conflict-free fragment LDS: banks 4g + t4).
// ---------------------------------------------------------------------------
#define AT_LDH 72                 // halves per smem row (36 words)
#define AT_WARP_WORDS (3 * 16 * 36)   // Qs + Ks + Vs per warp (1728 words)

__global__ void __launch_bounds__(128) attn_mma_kernel()
{
    __shared__ uint32_t smem[4][AT_WARP_WORDS];   // 27648 B

    const int warp = threadIdx.x >> 5;
    const int lane = threadIdx.x & 31;
    const int g    = lane >> 2;
    const int t4   = lane & 3;
    const int nh = blockIdx.x * 4 + warp;
    const int n  = nh >> 4;
    const int h  = nh & 15;
    const int b  = n >> 10;
    const int s  = n & 1023;

    __half* Qs = reinterpret_cast<__half*>(smem[warp]);   // [16][72]
    __half* Ks = Qs + 16 * AT_LDH;
    __half* Vs = Ks + 16 * AT_LDH;

    // ---- Load Q,K (with RoPE, lane owns dims lane & lane+32) and V (natural)
    const float co = g_rope_cos[lane];  // t=0 row handled in loop via table
    (void)co;
    #pragma unroll
    for (int t = 0; t < FRAMES; t++) {
        const size_t base = ((size_t)(((b * FRAMES + t) << 10) + s)) * QKV_N + h * HDIM;
        const float ql = __half2float(g_qkv_h[base + lane]);
        const float qh = __half2float(g_qkv_h[base + lane + 32]);
        const float kl = __half2float(g_qkv_h[base + HIDDEN + lane]);
        const float kh = __half2float(g_qkv_h[base + HIDDEN + lane + 32]);
        const float c  = g_rope_cos[t * 32 + lane];
        const float sn = g_rope_sin[t * 32 + lane];
        Qs[t * AT_LDH + lane]      = __float2half_rn(ql * c - qh * sn);
        Qs[t * AT_LDH + lane + 32] = __float2half_rn(qh * c + ql * sn);
        Ks[t * AT_LDH + lane]      = __float2half_rn(kl * c - kh * sn);
        Ks[t * AT_LDH + lane + 32] = __float2half_rn(kh * c + kl * sn);
        *reinterpret_cast<__half2*>(&Vs[t * AT_LDH + 2 * lane]) =
            *reinterpret_cast<const __half2*>(&g_qkv_h[base + 2 * HIDDEN + 2 * lane]);
    }
    __syncwarp();

    // ---- S = Q K^T  (tile0: k-frames 0-7, tile1: 8-15)
    float sT0[4] = {0.f, 0.f, 0.f, 0.f};
    float sT1[4] = {0.f, 0.f, 0.f, 0.f};
    #pragma unroll
    for (int kc = 0; kc < HDIM; kc += 16) {
        const uint32_t a0 = *reinterpret_cast<const uint32_t*>(&Qs[g * AT_LDH + kc + 2 * t4]);
        const uint32_t a1 = *reinterpret_cast<const uint32_t*>(&Qs[(g + 8) * AT_LDH + kc + 2 * t4]);
        const uint32_t a2 = *reinterpret_cast<const uint32_t*>(&Qs[g * AT_LDH + kc + 2 * t4 + 8]);
        const uint32_t a3 = *reinterpret_cast<const uint32_t*>(&Qs[(g + 8) * AT_LDH + kc + 2 * t4 + 8]);
        const uint32_t b00 = *reinterpret_cast<const uint32_t*>(&Ks[g * AT_LDH + kc + 2 * t4]);
        const uint32_t b01 = *reinterpret_cast<const uint32_t*>(&Ks[g * AT_LDH + kc + 2 * t4 + 8]);
        const uint32_t b10 = *reinterpret_cast<const uint32_t*>(&Ks[(g + 8) * AT_LDH + kc + 2 * t4]);
        const uint32_t b11 = *reinterpret_cast<const uint32_t*>(&Ks[(g + 8) * AT_LDH + kc + 2 * t4 + 8]);
        mma_f16(sT0, a0, a1, a2, a3, b00, b01);
        mma_f16(sT1, a0, a1, a2, a3, b10, b11);
    }

    // ---- scale + causal mask + softmax (rows g and g+8, 4 cols each per row)
    // Row r values: cols {2t4, 2t4+1, 8+2t4, 9+2t4}
    const int c0i = 2 * t4, c1i = 2 * t4 + 1, c2i = 8 + 2 * t4, c3i = 9 + 2 * t4;
    float r0v[4] = { sT0[0] * 0.125f, sT0[1] * 0.125f, sT1[0] * 0.125f, sT1[1] * 0.125f };
    float r1v[4] = { sT0[2] * 0.125f, sT0[3] * 0.125f, sT1[2] * 0.125f, sT1[3] * 0.125f };
    const int r0 = g, r1 = g + 8;
    if (c0i > r0) r0v[0] = -1e30f;
    if (c1i > r0) r0v[1] = -1e30f;
    if (c2i > r0) r0v[2] = -1e30f;
    if (c3i > r0) r0v[3] = -1e30f;
    if (c0i > r1) r1v[0] = -1e30f;
    if (c1i > r1) r1v[1] = -1e30f;
    if (c2i > r1) r1v[2] = -1e30f;
    if (c3i > r1) r1v[3] = -1e30f;

    float m0 = fmaxf(fmaxf(r0v[0], r0v[1]), fmaxf(r0v[2], r0v[3]));
    float m1 = fmaxf(fmaxf(r1v[0], r1v[1]), fmaxf(r1v[2], r1v[3]));
    m0 = fmaxf(m0, __shfl_xor_sync(0xffffffffu, m0, 1));
    m0 = fmaxf(m0, __shfl_xor_sync(0xffffffffu, m0, 2));
    m1 = fmaxf(m1, __shfl_xor_sync(0xffffffffu, m1, 1));
    m1 = fmaxf(m1, __shfl_xor_sync(0xffffffffu, m1, 2));

    #pragma unroll
    for (int j = 0; j < 4; j++) { r0v[j] = expf(r0v[j] - m0); r1v[j] = expf(r1v[j] - m1); }
    float s0 = r0v[0] + r0v[1] + r0v[2] + r0v[3];
    float s1 = r1v[0] + r1v[1] + r1v[2] + r1v[3];
    s0 += __shfl_xor_sync(0xffffffffu, s0, 1);
    s0 += __shfl_xor_sync(0xffffffffu, s0, 2);
    s1 += __shfl_xor_sync(0xffffffffu, s1, 1);
    s1 += __shfl_xor_sync(0xffffffffu, s1, 2);
    const float i0 = 1.0f / s0, i1 = 1.0f / s1;
    #pragma unroll
    for (int j = 0; j < 4; j++) { r0v[j] *= i0; r1v[j] *= i1; }

    // ---- P -> A-fragments (pure register packing)
    __half2 ph;
    uint32_t pa0, pa1, pa2, pa3;
    ph = __floats2half2_rn(r0v[0], r0v[1]); pa0 = *reinterpret_cast<uint32_t*>(&ph);
    ph = __floats2half2_rn(r1v[0], r1v[1]); pa1 = *reinterpret_cast<uint32_t*>(&ph);
    ph = __floats2half2_rn(r0v[2], r0v[3]); pa2 = *reinterpret_cast<uint32_t*>(&ph);
    ph = __floats2half2_rn(r1v[2], r1v[3]); pa3 = *reinterpret_cast<uint32_t*>(&ph);

    // ---- O = P V  (8 n-tiles of 8 dims); B-frags from natural-layout Vs
    float oacc[8][4];
    #pragma unroll
    for (int nt = 0; nt < 8; nt++) {
        oacc[nt][0] = oacc[nt][1] = oacc[nt][2] = oacc[nt][3] = 0.f;
        const int gp = nt * 8 + g;   // dim column
        __half2 bl = __halves2half2(Vs[(2 * t4)     * AT_LDH + gp],
                                    Vs[(2 * t4 + 1) * AT_LDH + gp]);
        __half2 bh = __halves2half2(Vs[(2 * t4 + 8) * AT_LDH + gp],
                                    Vs[(2 * t4 + 9) * AT_LDH + gp]);
        mma_f16(oacc[nt], pa0, pa1, pa2, pa3,
                *reinterpret_cast<uint32_t*>(&bl), *reinterpret_cast<uint32_t*>(&bh));
    }
    __syncwarp();

    // ---- O -> smem (reuse Qs region) as half2 rows [16][36 words]
    uint32_t* Os = smem[warp];
    #pragma unroll
    for (int nt = 0; nt < 8; nt++) {
        __half2 lo = __floats2half2_rn(oacc[nt][0], oacc[nt][1]);
        __half2 hi = __floats2half2_rn(oacc[nt][2], oacc[nt][3]);
        Os[g * 36 + 4 * nt + t4]       = *reinterpret_cast<uint32_t*>(&lo);
        Os[(g + 8) * 36 + 4 * nt + t4] = *reinterpret_cast<uint32_t*>(&hi);
    }
    __syncwarp();

    // ---- permuted coalesced global store: lane = pair index (0..31)
    const int pp = (lane & 24) | pslot(lane & 7);
    __half2* out2 = reinterpret_cast<__half2*>(g_attn_h);
    #pragma unroll
    for (int t = 0; t < FRAMES; t++) {
        const size_t tok = (size_t)(((b * FRAMES + t) << 10) + s);
        uint32_t w = Os[t * 36 + lane];
        out2[tok * (HIDDEN / 2) + h * 32 + pp] = *reinterpret_cast<__half2*>(&w);
    }
}

// ---------------------------------------------------------------------------
// Launch
// ---------------------------------------------------------------------------
extern "C" void kernel_launch(void* const* d_in, const int* in_sizes, int n_in,
                              void* d_out, int out_size)
{
    const float* x      = (const float*)d_in[0];
    const float* w_qkv  = (const float*)d_in[1];
    const float* w_out  = (const float*)d_in[2];
    const float* gamma  = (const float*)d_in[3];
    const float* beta   = (const float*)d_in[4];

    __half* xn_p;   cudaGetSymbolAddress((void**)&xn_p,   g_xn_h);
    __half* qkv_p;  cudaGetSymbolAddress((void**)&qkv_p,  g_qkv_h);
    __half* attn_p; cudaGetSymbolAddress((void**)&attn_p, g_attn_h);
    __half* wqkv_p; cudaGetSymbolAddress((void**)&wqkv_p, g_wqkv_h);
    __half* wout_p; cudaGetSymbolAddress((void**)&wout_p, g_wout_h);

    cudaFuncSetAttribute(gemm_h<true>,  cudaFuncAttributeMaxDynamicSharedMemorySize,
                         GEMM_SMEM_BYTES);
    cudaFuncSetAttribute(gemm_h<false>, cudaFuncAttributeMaxDynamicSharedMemorySize,
                         GEMM_SMEM_BYTES);

    // 0) RoPE tables + round+permute weights (tiny)
    rope_init<<<1, 512>>>();
    round_perm_w_h<<<QKV_N, 256>>>(w_qkv, (__half2*)wqkv_p);
    round_perm_w_h<<<HIDDEN, 256>>>(w_out, (__half2*)wout_p);

    // 1) LayerNorm -> fp16 permuted
    ln_kernel<<<NTOK, 256>>>(x, gamma, beta);

    // 2) QKV projection [fp16 m16n8k16 mma] -> fp16 qkv
    gemm_h<true><<<dim3(QKV_N / 128, NTOK / 128), 128, GEMM_SMEM_BYTES>>>(
        xn_p, wqkv_p, qkv_p, QKV_N);

    // 3) Tensor-core attention (RoPE + causal softmax + PV) -> fp16 permuted
    attn_mma_kernel<<<(NTOK * NHEADS / FRAMES) / 4, 128>>>();   // 8192 blocks

    // 4) Output projection -> d_out (fp32)
    gemm_h<false><<<dim3(HIDDEN / 128, NTOK / 128), 128, GEMM_SMEM_BYTES>>>(
        attn_p, wout_p, d_out, HIDDEN);
}

// round 17
// speedup vs baseline: 1.9628x; 1.0034x over previous
#include <cuda_runtime.h>
#include <cuda_fp16.h>
#include <math.h>
#include <stdint.h>

// Problem constants (hardcoded from reference setup_inputs)
#define BATCH   2
#define FRAMES  16
#define SPATIAL 1024            // height*width = 32*32
#define HIDDEN  1024
#define NHEADS  16
#define HDIM    64
#define NTOK    (BATCH*FRAMES*SPATIAL)   // 32768
#define QKV_N   (3*HIDDEN)               // 3072
#define LN_EPS  1e-5f

// Scratch buffers (device globals; no runtime allocation allowed)
__device__ __half g_xn_h[(size_t)NTOK * HIDDEN];      // 64 MB  (fp16, pair-permuted)
__device__ __half g_qkv_h[(size_t)NTOK * QKV_N];      // 201 MB (fp16, natural layout)
__device__ __half g_attn_h[(size_t)NTOK * HIDDEN];    // 64 MB  (fp16, pair-permuted)
__device__ __half g_wqkv_h[(size_t)QKV_N * HIDDEN];   // 6 MB   (fp16, pair-permuted)
__device__ __half g_wout_h[(size_t)HIDDEN * HIDDEN];  // 2 MB   (fp16, pair-permuted)
__device__ float  g_rope_cos[FRAMES * 32];            // RoPE tables
__device__ float  g_rope_sin[FRAMES * 32];

// Pair-level K-permutation: within each 16-element k-group (8 fp16 pairs),
// pair p -> slot (p<4 ? 2p : 2(p-4)+1). Fragment pairs (t4, t4+4) land adjacent.
__device__ __forceinline__ int pslot(int p) {   // p in 0..7
    return (p < 4) ? (2 * p) : (2 * (p - 4) + 1);
}

__device__ __forceinline__ void cp_async16(uint32_t saddr, const void* gaddr) {
    asm volatile("cp.async.cg.shared.global [%0], [%1], 16;" :: "r"(saddr), "l"(gaddr));
}

// ---------------------------------------------------------------------------
// RoPE table init: cos/sin(t * 10000^(-2i/64)) for t in 0..15, i in 0..31
// ---------------------------------------------------------------------------
__global__ void rope_init()
{
    const int tid = threadIdx.x;      // 0..511
    const int t = tid >> 5, i = tid & 31;
    const float inv_freq = expf(-(float)(2 * i) * (9.210340371976184f / 64.0f));
    const float fr = (float)t * inv_freq;
    g_rope_cos[tid] = cosf(fr);
    g_rope_sin[tid] = sinf(fr);
}

// ---------------------------------------------------------------------------
// Weight round+permute: fp32 row-major [rows,1024] -> fp16 pair-permuted.
// ---------------------------------------------------------------------------
__global__ void __launch_bounds__(256) round_perm_w_h(const float* __restrict__ w,
                                                      __half2* __restrict__ out)
{
    const int row = blockIdx.x;
    const int tid = threadIdx.x;
    const float4 v = reinterpret_cast<const float4*>(w + (size_t)row * HIDDEN)[tid];
    const int g16  = tid >> 2;                 // 16-elem group index (8 half2 words)
    const int pl   = 2 * (tid & 3);            // first pair index within group
    __half2* obase = out + (size_t)row * (HIDDEN / 2) + g16 * 8;
    obase[pslot(pl)]     = __floats2half2_rn(v.x, v.y);
    obase[pslot(pl + 1)] = __floats2half2_rn(v.z, v.w);
}

// ---------------------------------------------------------------------------
// LayerNorm: ONE WARP per token (8 tokens / 256-thread block).
// Pure shfl reduction — no smem, no __syncthreads. Output fp16 pair-permuted.
// ---------------------------------------------------------------------------
__global__ void __launch_bounds__(256) ln_kernel(const float* __restrict__ x,
                                                 const float* __restrict__ gamma,
                                                 const float* __restrict__ beta)
{
    const int warp = threadIdx.x >> 5;
    const int lane = threadIdx.x & 31;
    const int tok  = blockIdx.x * 8 + warp;

    const float4* xr = reinterpret_cast<const float4*>(x + (size_t)tok * HIDDEN);
    float4 v[8];
    float s = 0.f, ss = 0.f;
    #pragma unroll
    for (int w = 0; w < 8; w++) {
        v[w] = xr[w * 32 + lane];
        s  += v[w].x + v[w].y + v[w].z + v[w].w;
        ss += v[w].x*v[w].x + v[w].y*v[w].y + v[w].z*v[w].z + v[w].w*v[w].w;
    }
    #pragma unroll
    for (int o = 16; o > 0; o >>= 1) {
        s  += __shfl_xor_sync(0xffffffffu, s,  o);
        ss += __shfl_xor_sync(0xffffffffu, ss, o);
    }
    const float mean = s * (1.0f / HIDDEN);
    const float var  = ss * (1.0f / HIDDEN) - mean * mean;
    const float inv  = rsqrtf(var + LN_EPS);

    __half2* out = reinterpret_cast<__half2*>(g_xn_h) + (size_t)tok * (HIDDEN / 2);
    #pragma unroll
    for (int w = 0; w < 8; w++) {
        const int j = w * 32 + lane;              // float4 index (covers cols 4j..4j+3)
        const float4 gm = reinterpret_cast<const float4*>(gamma)[j];
        const float4 bt = reinterpret_cast<const float4*>(beta)[j];
        const float o0 = (v[w].x - mean) * inv * gm.x + bt.x;
        const float o1 = (v[w].y - mean) * inv * gm.y + bt.y;
        const float o2 = (v[w].z - mean) * inv * gm.z + bt.z;
        const float o3 = (v[w].w - mean) * inv * gm.w + bt.w;
        __half2* obase = out + (j >> 2) * 8;
        const int pl = 2 * (j & 3);
        obase[pslot(pl)]     = __floats2half2_rn(o0, o1);
        obase[pslot(pl + 1)] = __floats2half2_rn(o2, o3);
    }
}

// ---------------------------------------------------------------------------
// FP16 mma.sync helpers
// ---------------------------------------------------------------------------
__device__ __forceinline__ void mma_f16(float c[4],
                                        uint32_t a0, uint32_t a1, uint32_t a2, uint32_t a3,
                                        uint32_t b0, uint32_t b1)
{
    asm volatile(
        "mma.sync.aligned.m16n8k16.row.col.f32.f16.f16.f32 "
        "{%0,%1,%2,%3}, {%4,%5,%6,%7}, {%8,%9}, {%0,%1,%2,%3};"
        : "+f"(c[0]), "+f"(c[1]), "+f"(c[2]), "+f"(c[3])
        : "r"(a0), "r"(a1), "r"(a2), "r"(a3), "r"(b0), "r"(b1));
}

// ---------------------------------------------------------------------------
// FP16 mma.sync GEMM (NT), K=1024: C[m][n] = sum_k A[m][k]*B[n][k]
// (R13/R15 version — fastest proven GEMM.)
// ---------------------------------------------------------------------------
#define HK      1024
#define HBK     64
#define HNIT    (HK / HBK)      // 16
#define LDTW    40              // 4-byte words per smem row
#define AW      (128 * LDTW)    // words per matrix per stage (5120)
#define STGW    (2 * AW)        // words per stage (A+B)
#define GEMM_SMEM_BYTES (2 * STGW * 4)   // 81920

template<bool F16OUT>
__global__ void __launch_bounds__(128, 2)
gemm_h(const __half* __restrict__ A, const __half* __restrict__ B,
       void* __restrict__ Cv, int N)
{
    extern __shared__ uint32_t smem[];   // [2][STGW] words

    const int tid  = threadIdx.x;
    const int wid  = tid >> 5;
    const int lane = tid & 31;
    const int g    = lane >> 2;
    const int t4   = lane & 3;
    const int warpM = wid & 1;        // 0..1 -> 64 rows
    const int warpN = wid >> 1;       // 0..1 -> 64 cols

    const __half* Ab = A + (size_t)blockIdx.y * 128 * HK;
    const __half* Bb = B + (size_t)blockIdx.x * 128 * HK;

    const uint32_t smem_u = (uint32_t)__cvta_generic_to_shared(smem);

    int lrow[8], lch[8];
    #pragma unroll
    for (int j = 0; j < 8; j++) {
        const int lin = tid + j * 128;
        lrow[j] = lin >> 3;
        lch[j]  = lin & 7;
    }

    float acc[4][8][4];
    #pragma unroll
    for (int i = 0; i < 4; i++)
        #pragma unroll
        for (int j = 0; j < 8; j++)
            #pragma unroll
            for (int r = 0; r < 4; r++) acc[i][j][r] = 0.f;

    #pragma unroll
    for (int j = 0; j < 8; j++) {
        cp_async16(smem_u + (uint32_t)((lrow[j] * LDTW + lch[j] * 4) * 4),
                   Ab + (size_t)lrow[j] * HK + lch[j] * 8);
        cp_async16(smem_u + (uint32_t)((AW + lrow[j] * LDTW + lch[j] * 4) * 4),
                   Bb + (size_t)lrow[j] * HK + lch[j] * 8);
    }
    asm volatile("cp.async.commit_group;" ::: "memory");

    #pragma unroll 1
    for (int it = 0; it < HNIT; it++) {
        const int cur = it & 1;
        const int nxt = cur ^ 1;

        __syncthreads();

        if (it + 1 < HNIT) {
            const int k0 = (it + 1) * HBK;
            const uint32_t so = (uint32_t)(nxt * STGW) * 4u;
            #pragma unroll
            for (int j = 0; j < 8; j++) {
                cp_async16(smem_u + so + (uint32_t)((lrow[j] * LDTW + lch[j] * 4) * 4),
                           Ab + (size_t)lrow[j] * HK + k0 + lch[j] * 8);
                cp_async16(smem_u + so + (uint32_t)((AW + lrow[j] * LDTW + lch[j] * 4) * 4),
                           Bb + (size_t)lrow[j] * HK + k0 + lch[j] * 8);
            }
        }
        asm volatile("cp.async.commit_group;" ::: "memory");

        asm volatile("cp.async.wait_group 1;" ::: "memory");
        __syncthreads();

        const uint32_t* As = smem + cur * STGW;
        const uint32_t* Bs = As + AW;
        #pragma unroll
        for (int kg = 0; kg < HBK / 16; kg++) {
            const int kb = kg * 8;
            uint32_t af[4][4];
            #pragma unroll
            for (int mf = 0; mf < 4; mf++) {
                const int rb = warpM * 64 + mf * 16 + g;
                const uint2 lo = *reinterpret_cast<const uint2*>(&As[rb * LDTW + kb + 2 * t4]);
                const uint2 hi = *reinterpret_cast<const uint2*>(&As[(rb + 8) * LDTW + kb + 2 * t4]);
                af[mf][0] = lo.x;
                af[mf][1] = hi.x;
                af[mf][2] = lo.y;
                af[mf][3] = hi.y;
            }
            uint32_t bf[8][2];
            #pragma unroll
            for (int nfr = 0; nfr < 8; nfr++) {
                const int nb = warpN * 64 + nfr * 8 + g;
                const uint2 bb = *reinterpret_cast<const uint2*>(&Bs[nb * LDTW + kb + 2 * t4]);
                bf[nfr][0] = bb.x;
                bf[nfr][1] = bb.y;
            }
            #pragma unroll
            for (int mf = 0; mf < 4; mf++)
                #pragma unroll
                for (int nfr = 0; nfr < 8; nfr++)
                    mma_f16(acc[mf][nfr], af[mf][0], af[mf][1], af[mf][2], af[mf][3],
                            bf[nfr][0], bf[nfr][1]);
        }
    }

    const int m0 = blockIdx.y * 128 + warpM * 64;
    const int n0 = blockIdx.x * 128 + warpN * 64;
    if (F16OUT) {
        __half2* C = reinterpret_cast<__half2*>(Cv);
        #pragma unroll
        for (int mf = 0; mf < 4; mf++) {
            const int r0 = m0 + mf * 16 + g;
            #pragma unroll
            for (int nfr = 0; nfr < 8; nfr++) {
                const int c0 = n0 + nfr * 8 + t4 * 2;
                C[((size_t)r0 * N + c0) >> 1] =
                    __floats2half2_rn(acc[mf][nfr][0], acc[mf][nfr][1]);
                C[((size_t)(r0 + 8) * N + c0) >> 1] =
                    __floats2half2_rn(acc[mf][nfr][2], acc[mf][nfr][3]);
            }
        }
    } else {
        float* C = reinterpret_cast<float*>(Cv);
        #pragma unroll
        for (int mf = 0; mf < 4; mf++) {
            const int r0 = m0 + mf * 16 + g;
            #pragma unroll
            for (int nfr = 0; nfr < 8; nfr++) {
                const int c0 = n0 + nfr * 8 + t4 * 2;
                *reinterpret_cast<float2*>(C + (size_t)r0 * N + c0) =
                    make_float2(acc[mf][nfr][0], acc[mf][nfr][1]);
                *reinterpret_cast<float2*>(C + (size_t)(r0 + 8) * N + c0) =
                    make_float2(acc[mf][nfr][2], acc[mf][nfr][3]);
            }
        }
    }
}

// ---------------------------------------------------------------------------
// Tensor-core attention: ONE WARP per (n, h). 16-frame causal + RoPE.
// Q/K loaded as half2 (pair index = lane); RoPE rotate partner obtained via
// shfl_xor(lane,16) instead of a second scalar load. S = QK^T (2 MMAs/chunk),
// register softmax via quad shuffles, P repacked as A-frags, O = PV (8 MMAs).
// ---------------------------------------------------------------------------
#define AT_LDH 72                 // halves per smem row (36 words)
#define AT_WARP_WORDS (3 * 16 * 36)   // Qs + Ks + Vs per warp (1728 words)

__global__ void __launch_bounds__(128) attn_mma_kernel()
{
    __shared__ uint32_t smem[4][AT_WARP_WORDS];   // 27648 B

    const int warp = threadIdx.x >> 5;
    const int lane = threadIdx.x & 31;
    const int g    = lane >> 2;
    const int t4   = lane & 3;
    const int nh = blockIdx.x * 4 + warp;
    const int n  = nh >> 4;
    const int h  = nh & 15;
    const int b  = n >> 10;
    const int s  = n & 1023;

    __half* Qs = reinterpret_cast<__half*>(smem[warp]);   // [16][72]
    __half* Ks = Qs + 16 * AT_LDH;
    __half* Vs = Ks + 16 * AT_LDH;

    // ---- Load Q,K (half2 + shfl RoPE) and V (half2, natural)
    const __half2* qkv2 = reinterpret_cast<const __half2*>(g_qkv_h);
    const int i2 = (2 * lane) & 31;
    const float sgn = (lane < 16) ? -1.f : 1.f;
    #pragma unroll
    for (int t = 0; t < FRAMES; t++) {
        const size_t base2 = (((size_t)(((b * FRAMES + t) << 10) + s)) * QKV_N
                              + h * HDIM) >> 1;
        const __half2 q2 = qkv2[base2 + lane];
        const __half2 k2 = qkv2[base2 + 512 + lane];
        const __half2 v2 = qkv2[base2 + 1024 + lane];
        const uint32_t qpu = __shfl_xor_sync(0xffffffffu,
                                             *reinterpret_cast<const uint32_t*>(&q2), 16);
        const uint32_t kpu = __shfl_xor_sync(0xffffffffu,
                                             *reinterpret_cast<const uint32_t*>(&k2), 16);
        const float2 qf = __half22float2(q2);
        const float2 kf = __half22float2(k2);
        const float2 qp = __half22float2(*reinterpret_cast<const __half2*>(&qpu));
        const float2 kp = __half22float2(*reinterpret_cast<const __half2*>(&kpu));
        const float c0 = g_rope_cos[t * 32 + i2], c1 = g_rope_cos[t * 32 + i2 + 1];
        const float s0 = g_rope_sin[t * 32 + i2], s1 = g_rope_sin[t * 32 + i2 + 1];
        *reinterpret_cast<__half2*>(&Qs[t * AT_LDH + 2 * lane]) =
            __floats2half2_rn(qf.x * c0 + sgn * qp.x * s0, qf.y * c1 + sgn * qp.y * s1);
        *reinterpret_cast<__half2*>(&Ks[t * AT_LDH + 2 * lane]) =
            __floats2half2_rn(kf.x * c0 + sgn * kp.x * s0, kf.y * c1 + sgn * kp.y * s1);
        *reinterpret_cast<__half2*>(&Vs[t * AT_LDH + 2 * lane]) = v2;
    }
    __syncwarp();

    // ---- S = Q K^T  (tile0: k-frames 0-7, tile1: 8-15)
    float sT0[4] = {0.f, 0.f, 0.f, 0.f};
    float sT1[4] = {0.f, 0.f, 0.f, 0.f};
    #pragma unroll
    for (int kc = 0; kc < HDIM; kc += 16) {
        const uint32_t a0 = *reinterpret_cast<const uint32_t*>(&Qs[g * AT_LDH + kc + 2 * t4]);
        const uint32_t a1 = *reinterpret_cast<const uint32_t*>(&Qs[(g + 8) * AT_LDH + kc + 2 * t4]);
        const uint32_t a2 = *reinterpret_cast<const uint32_t*>(&Qs[g * AT_LDH + kc + 2 * t4 + 8]);
        const uint32_t a3 = *reinterpret_cast<const uint32_t*>(&Qs[(g + 8) * AT_LDH + kc + 2 * t4 + 8]);
        const uint32_t b00 = *reinterpret_cast<const uint32_t*>(&Ks[g * AT_LDH + kc + 2 * t4]);
        const uint32_t b01 = *reinterpret_cast<const uint32_t*>(&Ks[g * AT_LDH + kc + 2 * t4 + 8]);
        const uint32_t b10 = *reinterpret_cast<const uint32_t*>(&Ks[(g + 8) * AT_LDH + kc + 2 * t4]);
        const uint32_t b11 = *reinterpret_cast<const uint32_t*>(&Ks[(g + 8) * AT_LDH + kc + 2 * t4 + 8]);
        mma_f16(sT0, a0, a1, a2, a3, b00, b01);
        mma_f16(sT1, a0, a1, a2, a3, b10, b11);
    }

    // ---- scale + causal mask + softmax (rows g and g+8, 4 cols each per row)
    const int c0i = 2 * t4, c1i = 2 * t4 + 1, c2i = 8 + 2 * t4, c3i = 9 + 2 * t4;
    float r0v[4] = { sT0[0] * 0.125f, sT0[1] * 0.125f, sT1[0] * 0.125f, sT1[1] * 0.125f };
    float r1v[4] = { sT0[2] * 0.125f, sT0[3] * 0.125f, sT1[2] * 0.125f, sT1[3] * 0.125f };
    const int r0 = g, r1 = g + 8;
    if (c0i > r0) r0v[0] = -1e30f;
    if (c1i > r0) r0v[1] = -1e30f;
    if (c2i > r0) r0v[2] = -1e30f;
    if (c3i > r0) r0v[3] = -1e30f;
    if (c0i > r1) r1v[0] = -1e30f;
    if (c1i > r1) r1v[1] = -1e30f;
    if (c2i > r1) r1v[2] = -1e30f;
    if (c3i > r1) r1v[3] = -1e30f;

    float m0 = fmaxf(fmaxf(r0v[0], r0v[1]), fmaxf(r0v[2], r0v[3]));
    float m1 = fmaxf(fmaxf(r1v[0], r1v[1]), fmaxf(r1v[2], r1v[3]));
    m0 = fmaxf(m0, __shfl_xor_sync(0xffffffffu, m0, 1));
    m0 = fmaxf(m0, __shfl_xor_sync(0xffffffffu, m0, 2));
    m1 = fmaxf(m1, __shfl_xor_sync(0xffffffffu, m1, 1));
    m1 = fmaxf(m1, __shfl_xor_sync(0xffffffffu, m1, 2));

    #pragma unroll
    for (int j = 0; j < 4; j++) { r0v[j] = expf(r0v[j] - m0); r1v[j] = expf(r1v[j] - m1); }
    float s0r = r0v[0] + r0v[1] + r0v[2] + r0v[3];
    float s1r = r1v[0] + r1v[1] + r1v[2] + r1v[3];
    s0r += __shfl_xor_sync(0xffffffffu, s0r, 1);
    s0r += __shfl_xor_sync(0xffffffffu, s0r, 2);
    s1r += __shfl_xor_sync(0xffffffffu, s1r, 1);
    s1r += __shfl_xor_sync(0xffffffffu, s1r, 2);
    const float i0 = 1.0f / s0r, i1 = 1.0f / s1r;
    #pragma unroll
    for (int j = 0; j < 4; j++) { r0v[j] *= i0; r1v[j] *= i1; }

    // ---- P -> A-fragments (pure register packing)
    __half2 ph;
    uint32_t pa0, pa1, pa2, pa3;
    ph = __floats2half2_rn(r0v[0], r0v[1]); pa0 = *reinterpret_cast<uint32_t*>(&ph);
    ph = __floats2half2_rn(r1v[0], r1v[1]); pa1 = *reinterpret_cast<uint32_t*>(&ph);
    ph = __floats2half2_rn(r0v[2], r0v[3]); pa2 = *reinterpret_cast<uint32_t*>(&ph);
    ph = __floats2half2_rn(r1v[2], r1v[3]); pa3 = *reinterpret_cast<uint32_t*>(&ph);

    // ---- O = P V  (8 n-tiles of 8 dims); B-frags from natural-layout Vs
    float oacc[8][4];
    #pragma unroll
    for (int nt = 0; nt < 8; nt++) {
        oacc[nt][0] = oacc[nt][1] = oacc[nt][2] = oacc[nt][3] = 0.f;
        const int gp = nt * 8 + g;   // dim column
        __half2 bl = __halves2half2(Vs[(2 * t4)     * AT_LDH + gp],
                                    Vs[(2 * t4 + 1) * AT_LDH + gp]);
        __half2 bh = __halves2half2(Vs[(2 * t4 + 8) * AT_LDH + gp],
                                    Vs[(2 * t4 + 9) * AT_LDH + gp]);
        mma_f16(oacc[nt], pa0, pa1, pa2, pa3,
                *reinterpret_cast<uint32_t*>(&bl), *reinterpret_cast<uint32_t*>(&bh));
    }
    __syncwarp();

    // ---- O -> smem (reuse Qs region) as half2 rows [16][36 words]
    uint32_t* Os = smem[warp];
    #pragma unroll
    for (int nt = 0; nt < 8; nt++) {
        __half2 lo = __floats2half2_rn(oacc[nt][0], oacc[nt][1]);
        __half2 hi = __floats2half2_rn(oacc[nt][2], oacc[nt][3]);
        Os[g * 36 + 4 * nt + t4]       = *reinterpret_cast<uint32_t*>(&lo);
        Os[(g + 8) * 36 + 4 * nt + t4] = *reinterpret_cast<uint32_t*>(&hi);
    }
    __syncwarp();

    // ---- permuted coalesced global store: lane = pair index (0..31)
    const int pp = (lane & 24) | pslot(lane & 7);
    __half2* out2 = reinterpret_cast<__half2*>(g_attn_h);
    #pragma unroll
    for (int t = 0; t < FRAMES; t++) {
        const size_t tok = (size_t)(((b * FRAMES + t) << 10) + s);
        uint32_t w = Os[t * 36 + lane];
        out2[tok * (HIDDEN / 2) + h * 32 + pp] = *reinterpret_cast<__half2*>(&w);
    }
}

// ---------------------------------------------------------------------------
// Launch
// ---------------------------------------------------------------------------
extern "C" void kernel_launch(void* const* d_in, const int* in_sizes, int n_in,
                              void* d_out, int out_size)
{
    const float* x      = (const float*)d_in[0];
    const float* w_qkv  = (const float*)d_in[1];
    const float* w_out  = (const float*)d_in[2];
    const float* gamma  = (const float*)d_in[3];
    const float* beta   = (const float*)d_in[4];

    __half* xn_p;   cudaGetSymbolAddress((void**)&xn_p,   g_xn_h);
    __half* qkv_p;  cudaGetSymbolAddress((void**)&qkv_p,  g_qkv_h);
    __half* attn_p; cudaGetSymbolAddress((void**)&attn_p, g_attn_h);
    __half* wqkv_p; cudaGetSymbolAddress((void**)&wqkv_p, g_wqkv_h);
    __half* wout_p; cudaGetSymbolAddress((void**)&wout_p, g_wout_h);

    cudaFuncSetAttribute(gemm_h<true>,  cudaFuncAttributeMaxDynamicSharedMemorySize,
                         GEMM_SMEM_BYTES);
    cudaFuncSetAttribute(gemm_h<false>, cudaFuncAttributeMaxDynamicSharedMemorySize,
                         GEMM_SMEM_BYTES);

    // 0) RoPE tables + round+permute weights (tiny)
    rope_init<<<1, 512>>>();
    round_perm_w_h<<<QKV_N, 256>>>(w_qkv, (__half2*)wqkv_p);
    round_perm_w_h<<<HIDDEN, 256>>>(w_out, (__half2*)wout_p);

    // 1) LayerNorm (warp-per-token, shfl-only) -> fp16 permuted
    ln_kernel<<<NTOK / 8, 256>>>(x, gamma, beta);

    // 2) QKV projection [fp16 m16n8k16 mma] -> fp16 qkv
    gemm_h<true><<<dim3(QKV_N / 128, NTOK / 128), 128, GEMM_SMEM_BYTES>>>(
        xn_p, wqkv_p, qkv_p, QKV_N);

    // 3) Tensor-core attention (RoPE + causal softmax + PV) -> fp16 permuted
    attn_mma_kernel<<<(NTOK * NHEADS / FRAMES) / 4, 128>>>();   // 8192 blocks

    // 4) Output projection -> d_out (fp32)
    gemm_h<false><<<dim3(HIDDEN / 128, NTOK / 128), 128, GEMM_SMEM_BYTES>>>(
        attn_p, wout_p, d_out, HIDDEN);
}